// round 5
// baseline (speedup 1.0000x reference)
#include <cuda_runtime.h>

// OMul: r[i] = outer(x[i], y[i]) flattened.
// x: [N, 256] f32, y: [N, 256] f32, out: [N, 65536] f32.
// Pure HBM-write-bound: 1 GiB of output stores.
//
// R5: exact R2 winner shape (grid=4096, 1 row/CTA, smem-staged inputs,
// warp-uniform LDS broadcast, 512B contiguous per warp per iteration),
// single change: default write-back stores instead of __stcs streaming.
// A/B to resolve whether eager .cs eviction was costing DRAM scheduling
// efficiency vs letting the 126MB L2 batch-drain write-back traffic.

static constexpr int M = 256;
static constexpr int K = 256;
static constexpr int THREADS = 256;

__global__ __launch_bounds__(THREADS, 8)
void omul_kernel(const float* __restrict__ x,
                 const float* __restrict__ y,
                 float* __restrict__ out)
{
    __shared__ float sx[M];
    __shared__ float sy[K];

    const int row = blockIdx.x;
    const int t   = threadIdx.x;

    sx[t] = x[(size_t)row * M + t];
    sy[t] = y[(size_t)row * K + t];
    __syncthreads();

    const int k4 = t & 63;        // which float4 chunk of k (0..63)
    const int m0 = t >> 6;        // 0..3: m offset within group of 4

    const float4 y4 = reinterpret_cast<const float4*>(sy)[k4];

    float4* out4 = reinterpret_cast<float4*>(out + (size_t)row * (M * K));

    #pragma unroll 8
    for (int mi = 0; mi < 64; mi++) {
        const int m = m0 + mi * 4;
        const float xv = sx[m];     // warp-uniform broadcast
        float4 v;
        v.x = xv * y4.x;
        v.y = xv * y4.y;
        v.z = xv * y4.z;
        v.w = xv * y4.w;
        // default write-back store: let L2 buffer and batch-drain to DRAM
        out4[(size_t)m * 64 + k4] = v;
    }
}

extern "C" void kernel_launch(void* const* d_in, const int* in_sizes, int n_in,
                              void* d_out, int out_size)
{
    const float* x = (const float*)d_in[0];
    const float* y = (const float*)d_in[1];
    float* out = (float*)d_out;

    const int n = in_sizes[0] / M;   // 4096 rows

    omul_kernel<<<n, THREADS>>>(x, y, out);
}

// round 6
// speedup vs baseline: 1.3007x; 1.3007x over previous
#include <cuda_runtime.h>
#include <cstdint>

// OMul: r[i] = outer(x[i], y[i]) flattened.
// x: [N, 256] f32, y: [N, 256] f32, out: [N, 65536] f32.
// Pure HBM-write-bound: 1 GiB of output stores.
//
// R6: R2 champion shape (grid=4096, 1 row/CTA, smem-staged inputs,
// warp-uniform x broadcast, .cs streaming stores) upgraded to 256-bit
// stores (st.global.cs.v8.b32, sm_100+): 32 STG.256 per thread instead of
// 64 STG.128; each warp writes 1KB contiguous per store instruction.
//
// Layout: thread t, warp w = t>>5, lane l = t&31.
//   iteration i (0..31): m = w + 8*i  (warp-uniform), thread writes
//   out[row*65536 + m*256 + l*8 .. +7]  (32B chunk, 32B-aligned).

static constexpr int M = 256;
static constexpr int K = 256;
static constexpr int THREADS = 256;

__device__ __forceinline__ void stg_cs_v8(float* ptr,
                                          float a0, float a1, float a2, float a3,
                                          float a4, float a5, float a6, float a7)
{
    asm volatile(
        "st.global.cs.v8.b32 [%0], {%1, %2, %3, %4, %5, %6, %7, %8};"
        :: "l"(ptr),
           "r"(__float_as_uint(a0)), "r"(__float_as_uint(a1)),
           "r"(__float_as_uint(a2)), "r"(__float_as_uint(a3)),
           "r"(__float_as_uint(a4)), "r"(__float_as_uint(a5)),
           "r"(__float_as_uint(a6)), "r"(__float_as_uint(a7))
        : "memory");
}

__global__ __launch_bounds__(THREADS, 8)
void omul_kernel(const float* __restrict__ x,
                 const float* __restrict__ y,
                 float* __restrict__ out)
{
    __shared__ float sx[M];
    __shared__ float sy[K];

    const int row = blockIdx.x;
    const int t   = threadIdx.x;

    sx[t] = x[(size_t)row * M + t];
    sy[t] = y[(size_t)row * K + t];
    __syncthreads();

    const int w = t >> 5;         // warp id (0..7)
    const int l = t & 31;         // lane

    // Each thread owns k chunk [l*8, l*8+8): preload 8 y values.
    const float4 ya = reinterpret_cast<const float4*>(sy)[l * 2 + 0];
    const float4 yb = reinterpret_cast<const float4*>(sy)[l * 2 + 1];

    float* orow = out + (size_t)row * (M * K) + l * 8;

    #pragma unroll 8
    for (int i = 0; i < 32; i++) {
        const int m = w + i * 8;
        const float xv = sx[m];     // warp-uniform smem broadcast
        stg_cs_v8(orow + (size_t)m * K,
                  xv * ya.x, xv * ya.y, xv * ya.z, xv * ya.w,
                  xv * yb.x, xv * yb.y, xv * yb.z, xv * yb.w);
    }
}

extern "C" void kernel_launch(void* const* d_in, const int* in_sizes, int n_in,
                              void* d_out, int out_size)
{
    const float* x = (const float*)d_in[0];
    const float* y = (const float*)d_in[1];
    float* out = (float*)d_out;

    const int n = in_sizes[0] / M;   // 4096 rows

    omul_kernel<<<n, THREADS>>>(x, y, out);
}